// round 15
// baseline (speedup 1.0000x reference)
#include <cuda_runtime.h>
#include <cuda_fp16.h>
#include <cstdint>

// ---------------- problem constants ----------------------------------------
// B=2, C=256, N=4096, NUM_HEAD=4, D=8, AT_HEAD=64, BH=8
#define NTOK   4096
#define BH_CNT 8
#define LOG2E  1.4426950408889634f

#define N_ITEMS 512          // attn work items: bh(8) x mb(64 blocks of 64 m)
#define PERSIST 296          // persistent attn CTAs (2 per SM)

// ---------------- device scratch (no allocation allowed) -------------------
__device__ __half g_Qh[BH_CNT * NTOK * 8];
__device__ __half g_Kh[BH_CNT * NTOK * 8];
__device__ __half g_VT[BH_CNT * 8 * NTOK];
__device__ float  g_O [BH_CNT * NTOK * 8];
__device__ unsigned g_ticket;   // attn work queue (reset by qkv each launch)

// ============================================================================
// Kernel 1: HMMA QKV projection. (R14-proven: 12.3 us) + ticket reset.
// ============================================================================
#define XS_STRIDE 264   // halves per xs row

__global__ void __launch_bounds__(256, 2) qkv_kernel(
    const float* __restrict__ x,
    const float* __restrict__ Wq, const float* __restrict__ bq,
    const float* __restrict__ Wk, const float* __restrict__ bk,
    const float* __restrict__ Wv, const float* __restrict__ bv)
{
    __shared__ __align__(16) __half    xs[32 * XS_STRIDE];  // 16.9 KB
    __shared__ __align__(16) uint32_t  ws32[32 * 104];      // 13.3 KB
    __shared__ float bias_s[96];

    if (blockIdx.x == 0 && threadIdx.x == 0) g_ticket = 0;

    const int b    = blockIdx.x >> 7;
    const int n0   = (blockIdx.x & 127) * 32;
    const int tid  = threadIdx.x;
    const int warp = tid >> 5;
    const int lane = tid & 31;
    const int g    = lane >> 2;
    const int q4   = lane & 3;
    const int mt   = warp & 1;
    const int nh   = warp >> 1;

    if (tid < 96) {
        float bv_;
        if (tid < 32)      bv_ = __ldg(&bq[tid]);
        else if (tid < 64) bv_ = __ldg(&bk[tid - 32]);
        else               bv_ = __ldg(&bv[tid - 64]);
        bias_s[tid] = bv_;
    }

    // stage x^T tile: f16 [n][c]; coalesced LDG.32 over n, pack c-pairs
    {
        const int sn = lane;
        const int sg = warp;
        const float* xb = x + (size_t)(b * 256 + sg * 32) * NTOK + n0 + sn;
#pragma unroll
        for (int c2 = 0; c2 < 16; ++c2) {
            float f0 = __ldg(xb + (2 * c2)     * NTOK);
            float f1 = __ldg(xb + (2 * c2 + 1) * NTOK);
            __half2 h2 = __floats2half2_rn(f0, f1);
            *(__half2*)&xs[sn * XS_STRIDE + sg * 32 + 2 * c2] = h2;
        }
    }

    float acc[3][4];
#pragma unroll
    for (int j = 0; j < 3; ++j)
#pragma unroll
        for (int i = 0; i < 4; ++i) acc[j][i] = 0.0f;

    for (int kc = 0; kc < 4; ++kc) {
        __syncthreads();
#pragma unroll
        for (int t = 0; t < 6; ++t) {
            int idx = tid + t * 256;
            int r   = idx >> 4;
            int kq  = idx & 15;
            const float* base = (r < 32) ? Wq : ((r < 64) ? Wk : Wv);
            float4 w = __ldg((const float4*)(base + (r & 31) * 256 + kc * 64) + kq);
            __half2 h0 = __floats2half2_rn(w.x, w.y);
            __half2 h1 = __floats2half2_rn(w.z, w.w);
            ws32[(kq * 2)     * 104 + r] = *(uint32_t*)&h0;
            ws32[(kq * 2 + 1) * 104 + r] = *(uint32_t*)&h1;
        }
        __syncthreads();

#pragma unroll
        for (int k8 = 0; k8 < 8; ++k8) {
            const int cbase = kc * 64 + k8 * 8 + 2 * q4;
            uint32_t a0 = *(const uint32_t*)&xs[(mt * 16 + g)     * XS_STRIDE + cbase];
            uint32_t a1 = *(const uint32_t*)&xs[(mt * 16 + g + 8) * XS_STRIDE + cbase];
            const uint32_t* wrow = &ws32[(k8 * 4 + q4) * 104];
#pragma unroll
            for (int j = 0; j < 3; ++j) {
                uint32_t bf = wrow[(nh * 3 + j) * 8 + g];
                asm volatile(
                    "mma.sync.aligned.m16n8k8.row.col.f32.f16.f16.f32 "
                    "{%0,%1,%2,%3}, {%4,%5}, {%6}, {%0,%1,%2,%3};"
                    : "+f"(acc[j][0]), "+f"(acc[j][1]), "+f"(acc[j][2]), "+f"(acc[j][3])
                    : "r"(a0), "r"(a1), "r"(bf));
            }
        }
    }

    const int nA = n0 + mt * 16 + g;
    const int nB = nA + 8;
#pragma unroll
    for (int j = 0; j < 3; ++j) {
        int tile = nh * 3 + j;
        int p = tile >> 2;
        int h = tile & 3;
        int d = 2 * q4;
        int bh = b * 4 + h;
        float b0 = bias_s[tile * 8 + d];
        float b1 = bias_s[tile * 8 + d + 1];
        float v00 = acc[j][0] + b0, v01 = acc[j][1] + b1;
        float v10 = acc[j][2] + b0, v11 = acc[j][3] + b1;
        if (p == 0) {
            v00 *= LOG2E; v01 *= LOG2E; v10 *= LOG2E; v11 *= LOG2E;
            *(__half2*)&g_Qh[((size_t)bh * NTOK + nA) * 8 + d] = __floats2half2_rn(v00, v01);
            *(__half2*)&g_Qh[((size_t)bh * NTOK + nB) * 8 + d] = __floats2half2_rn(v10, v11);
        } else if (p == 1) {
            *(__half2*)&g_Kh[((size_t)bh * NTOK + nA) * 8 + d] = __floats2half2_rn(v00, v01);
            *(__half2*)&g_Kh[((size_t)bh * NTOK + nB) * 8 + d] = __floats2half2_rn(v10, v11);
        } else {
            __half* vt0 = g_VT + ((size_t)bh * 8 + d)     * NTOK;
            __half* vt1 = g_VT + ((size_t)bh * 8 + d + 1) * NTOK;
            vt0[nA] = __float2half_rn(v00);
            vt1[nA] = __float2half_rn(v01);
            vt0[nB] = __float2half_rn(v10);
            vt1[nB] = __float2half_rn(v11);
        }
    }
}

// ============================================================================
// Kernel 2: persistent fine-grained HMMA attention.
// 296 CTAs (2/SM) x 128 threads (4 warps x 16 m = 64-m items), dynamic ticket
// over 512 items (bh-major for L2 slab reuse). Math identical to R13/R14:
//   GEMM1 f16-accum (2x m16n8k8) -> ex2.f16x2 -> GEMM2a E·V + GEMM2b E·ones.
// ============================================================================
#define VPAD 520   // sVT row stride in halves

__global__ void __launch_bounds__(128, 2) attn_kernel()
{
    __shared__ __align__(16) __half sQ[512 * 8];      // 8 KB
    __shared__ __align__(16) __half sVT[8 * VPAD];    // 8.1 KB
    __shared__ unsigned s_item;

    const int tid  = threadIdx.x;
    const int warp = tid >> 5;
    const int lane = tid & 31;
    const int g    = lane >> 2;
    const int q4   = lane & 3;
    const uint32_t bOnes = (g == 0) ? 0x3C003C00u : 0u;
    const int vd = tid >> 4;     // V staging: d row (8 groups of 16 threads)
    const int vj = tid & 15;

    for (;;) {
        if (tid == 0) s_item = atomicAdd(&g_ticket, 1u);
        __syncthreads();                 // publish s_item; smem safe to reuse
        const unsigned it = s_item;
        if (it >= N_ITEMS) return;

        const int bh = it >> 6;          // bh-major: concurrent items share slabs in L2
        const int mb = it & 63;
        const int m0 = mb * 64 + warp * 16;

        const __half* Kbase = g_Kh + (size_t)bh * NTOK * 8;
        const uint32_t aK0 = *(const uint32_t*)(Kbase + (m0 + g) * 8 + q4 * 2);
        const uint32_t aK1 = *(const uint32_t*)(Kbase + (m0 + g + 8) * 8 + q4 * 2);

        float o0 = 0.f, o1 = 0.f, o2 = 0.f, o3 = 0.f;
        float p0 = 0.f, p1 = 0.f, p2 = 0.f, p3 = 0.f;

        for (int ns = 0; ns < 8; ++ns) {
            __syncthreads();             // previous inner loop done with smem
            // stage Q slab: 512 float4 over 128 threads
            {
                const float4* Qs = (const float4*)(g_Qh + (size_t)bh * NTOK * 8 + ns * 512 * 8);
#pragma unroll
                for (int t = 0; t < 4; ++t)
                    ((float4*)sQ)[tid + t * 128] = Qs[tid + t * 128];
            }
            // stage V slab: 8 rows x 64 float4; 16 threads per row
            {
                const float4* Vs = (const float4*)(g_VT + (size_t)(bh * 8 + vd) * NTOK + ns * 512);
                float4* dst = (float4*)(sVT + vd * VPAD);
#pragma unroll
                for (int t = 0; t < 4; ++t)
                    dst[vj + t * 16] = Vs[vj + t * 16];
            }
            __syncthreads();

#pragma unroll 4
            for (int p = 0; p < 32; ++p) {
                const int n0 = p * 16;
                uint32_t bQ0 = *(const uint32_t*)(sQ + (n0 + g) * 8 + q4 * 2);
                uint32_t bQ1 = *(const uint32_t*)(sQ + (n0 + 8 + g) * 8 + q4 * 2);
                uint32_t bV0 = *(const uint32_t*)(sVT + g * VPAD + n0 + q4 * 2);
                uint32_t bV1 = *(const uint32_t*)(sVT + g * VPAD + n0 + 8 + q4 * 2);

                uint32_t e0, e1, e2, e3;
                asm volatile(
                    "mma.sync.aligned.m16n8k8.row.col.f16.f16.f16.f16 "
                    "{%0,%1}, {%2,%3}, {%4}, {%5,%6};"
                    : "=r"(e0), "=r"(e1)
                    : "r"(aK0), "r"(aK1), "r"(bQ0), "r"(0u), "r"(0u));
                asm volatile(
                    "mma.sync.aligned.m16n8k8.row.col.f16.f16.f16.f16 "
                    "{%0,%1}, {%2,%3}, {%4}, {%5,%6};"
                    : "=r"(e2), "=r"(e3)
                    : "r"(aK0), "r"(aK1), "r"(bQ1), "r"(0u), "r"(0u));

                asm("ex2.approx.f16x2 %0, %1;" : "=r"(e0) : "r"(e0));
                asm("ex2.approx.f16x2 %0, %1;" : "=r"(e1) : "r"(e1));
                asm("ex2.approx.f16x2 %0, %1;" : "=r"(e2) : "r"(e2));
                asm("ex2.approx.f16x2 %0, %1;" : "=r"(e3) : "r"(e3));

                asm volatile(
                    "mma.sync.aligned.m16n8k16.row.col.f32.f16.f16.f32 "
                    "{%0,%1,%2,%3}, {%4,%5,%6,%7}, {%8,%9}, {%0,%1,%2,%3};"
                    : "+f"(o0), "+f"(o1), "+f"(o2), "+f"(o3)
                    : "r"(e0), "r"(e1), "r"(e2), "r"(e3), "r"(bV0), "r"(bV1));
                asm volatile(
                    "mma.sync.aligned.m16n8k16.row.col.f32.f16.f16.f32 "
                    "{%0,%1,%2,%3}, {%4,%5,%6,%7}, {%8,%9}, {%0,%1,%2,%3};"
                    : "+f"(p0), "+f"(p1), "+f"(p2), "+f"(p3)
                    : "r"(e0), "r"(e1), "r"(e2), "r"(e3), "r"(bOnes), "r"(bOnes));
            }
        }

        const float denA = __shfl_sync(0xFFFFFFFFu, p0, g * 4);
        const float denB = __shfl_sync(0xFFFFFFFFu, p2, g * 4);
        (void)p1; (void)p3;
        const float rA = 1.0f / denA;
        const float rB = 1.0f / denB;

        float* OpA = g_O + ((size_t)(bh * NTOK + m0 + g)) * 8 + q4 * 2;
        float* OpB = g_O + ((size_t)(bh * NTOK + m0 + g + 8)) * 8 + q4 * 2;
        *(float2*)OpA = make_float2(o0 * rA, o1 * rA);
        *(float2*)OpB = make_float2(o2 * rB, o3 * rB);
    }
}

// ============================================================================
// Kernel 3: Wo projection + bias + gamma + residual. (unchanged)
// ============================================================================
__global__ void __launch_bounds__(256) out_kernel(
    const float* __restrict__ x,
    const float* __restrict__ Wo, const float* __restrict__ bo,
    const float* __restrict__ gamma,
    float* __restrict__ out)
{
    __shared__ float wo_s[256];
    __shared__ float bo_s[32];
    __shared__ float gam_s;

    const int t  = blockIdx.x * 256 + threadIdx.x;
    const int m  = t & 4095;
    const int bh = (t >> 12) & 7;
    const int eh = t >> 15;
    const int b  = bh >> 2;
    const int h  = bh & 3;

    wo_s[threadIdx.x] = Wo[h * 512 + eh * 256 + threadIdx.x];
    if (threadIdx.x < 32) bo_s[threadIdx.x] = bo[h * 64 + eh * 32 + threadIdx.x];
    if (threadIdx.x == 0) gam_s = gamma[h];
    __syncthreads();

    const float4* op = (const float4*)(g_O + (size_t)(bh * NTOK + m) * 8);
    float4 a = op[0], c = op[1];
    float o[8] = {a.x, a.y, a.z, a.w, c.x, c.y, c.z, c.w};

    const float gam = gam_s;
#pragma unroll 4
    for (int e = 0; e < 32; ++e) {
        float y = bo_s[e];
#pragma unroll
        for (int d = 0; d < 8; ++d) y += wo_s[e * 8 + d] * o[d];
        int idx = b * (256 * NTOK) + (h * 64 + eh * 32 + e) * NTOK + m;
        out[idx] = gam * y + x[idx];
    }
}

// ============================================================================
extern "C" void kernel_launch(void* const* d_in, const int* in_sizes, int n_in,
                              void* d_out, int out_size)
{
    const float* x     = (const float*)d_in[0];
    const float* Wq    = (const float*)d_in[1];
    const float* bq    = (const float*)d_in[2];
    const float* Wk    = (const float*)d_in[3];
    const float* bk    = (const float*)d_in[4];
    const float* Wv    = (const float*)d_in[5];
    const float* bv    = (const float*)d_in[6];
    const float* Wo    = (const float*)d_in[7];
    const float* bo    = (const float*)d_in[8];
    const float* gamma = (const float*)d_in[9];
    float* out = (float*)d_out;

    qkv_kernel<<<256, 256>>>(x, Wq, bq, Wk, bk, Wv, bv);
    attn_kernel<<<PERSIST, 128>>>();
    out_kernel<<<256, 256>>>(x, Wo, bo, gamma, out);
}

// round 16
// speedup vs baseline: 1.2029x; 1.2029x over previous
#include <cuda_runtime.h>
#include <cuda_fp16.h>
#include <cstdint>

// ---------------- problem constants ----------------------------------------
// B=2, C=256, N=4096, NUM_HEAD=4, D=8, AT_HEAD=64, BH=8
#define NTOK   4096
#define BH_CNT 8
#define LOG2E  1.4426950408889634f

// ---------------- device scratch (no allocation allowed) -------------------
__device__ __half g_Qh[BH_CNT * NTOK * 8];
__device__ __half g_Kh[BH_CNT * NTOK * 8];
__device__ __half g_VT[BH_CNT * 8 * NTOK];
// attention partials per n-half: unnormalized numerators + denominators
__device__ float  g_Pn[2 * BH_CNT * NTOK * 8];
__device__ float  g_Pd[2 * BH_CNT * NTOK];

// ============================================================================
// Kernel 1: HMMA QKV projection. (R14-proven: 12.3 us)
// C^T[n][96] = X^T[n][256] · W^T[256][96]; emits f16 q/k ([n][8]) and vT.
// ============================================================================
#define XS_STRIDE 264   // halves per xs row

__global__ void __launch_bounds__(256, 2) qkv_kernel(
    const float* __restrict__ x,
    const float* __restrict__ Wq, const float* __restrict__ bq,
    const float* __restrict__ Wk, const float* __restrict__ bk,
    const float* __restrict__ Wv, const float* __restrict__ bv)
{
    __shared__ __align__(16) __half    xs[32 * XS_STRIDE];  // 16.9 KB
    __shared__ __align__(16) uint32_t  ws32[32 * 104];      // 13.3 KB
    __shared__ float bias_s[96];

    const int b    = blockIdx.x >> 7;
    const int n0   = (blockIdx.x & 127) * 32;
    const int tid  = threadIdx.x;
    const int warp = tid >> 5;
    const int lane = tid & 31;
    const int g    = lane >> 2;
    const int q4   = lane & 3;
    const int mt   = warp & 1;
    const int nh   = warp >> 1;

    if (tid < 96) {
        float bv_;
        if (tid < 32)      bv_ = __ldg(&bq[tid]);
        else if (tid < 64) bv_ = __ldg(&bk[tid - 32]);
        else               bv_ = __ldg(&bv[tid - 64]);
        bias_s[tid] = bv_;
    }

    // stage x^T tile: f16 [n][c]; coalesced LDG.32 over n, pack c-pairs
    {
        const int sn = lane;
        const int sg = warp;
        const float* xb = x + (size_t)(b * 256 + sg * 32) * NTOK + n0 + sn;
#pragma unroll
        for (int c2 = 0; c2 < 16; ++c2) {
            float f0 = __ldg(xb + (2 * c2)     * NTOK);
            float f1 = __ldg(xb + (2 * c2 + 1) * NTOK);
            __half2 h2 = __floats2half2_rn(f0, f1);
            *(__half2*)&xs[sn * XS_STRIDE + sg * 32 + 2 * c2] = h2;
        }
    }

    float acc[3][4];
#pragma unroll
    for (int j = 0; j < 3; ++j)
#pragma unroll
        for (int i = 0; i < 4; ++i) acc[j][i] = 0.0f;

    for (int kc = 0; kc < 4; ++kc) {
        __syncthreads();
#pragma unroll
        for (int t = 0; t < 6; ++t) {
            int idx = tid + t * 256;
            int r   = idx >> 4;
            int kq  = idx & 15;
            const float* base = (r < 32) ? Wq : ((r < 64) ? Wk : Wv);
            float4 w = __ldg((const float4*)(base + (r & 31) * 256 + kc * 64) + kq);
            __half2 h0 = __floats2half2_rn(w.x, w.y);
            __half2 h1 = __floats2half2_rn(w.z, w.w);
            ws32[(kq * 2)     * 104 + r] = *(uint32_t*)&h0;
            ws32[(kq * 2 + 1) * 104 + r] = *(uint32_t*)&h1;
        }
        __syncthreads();

#pragma unroll
        for (int k8 = 0; k8 < 8; ++k8) {
            const int cbase = kc * 64 + k8 * 8 + 2 * q4;
            uint32_t a0 = *(const uint32_t*)&xs[(mt * 16 + g)     * XS_STRIDE + cbase];
            uint32_t a1 = *(const uint32_t*)&xs[(mt * 16 + g + 8) * XS_STRIDE + cbase];
            const uint32_t* wrow = &ws32[(k8 * 4 + q4) * 104];
#pragma unroll
            for (int j = 0; j < 3; ++j) {
                uint32_t bf = wrow[(nh * 3 + j) * 8 + g];
                asm volatile(
                    "mma.sync.aligned.m16n8k8.row.col.f32.f16.f16.f32 "
                    "{%0,%1,%2,%3}, {%4,%5}, {%6}, {%0,%1,%2,%3};"
                    : "+f"(acc[j][0]), "+f"(acc[j][1]), "+f"(acc[j][2]), "+f"(acc[j][3])
                    : "r"(a0), "r"(a1), "r"(bf));
            }
        }
    }

    const int nA = n0 + mt * 16 + g;
    const int nB = nA + 8;
#pragma unroll
    for (int j = 0; j < 3; ++j) {
        int tile = nh * 3 + j;
        int p = tile >> 2;
        int h = tile & 3;
        int d = 2 * q4;
        int bh = b * 4 + h;
        float b0 = bias_s[tile * 8 + d];
        float b1 = bias_s[tile * 8 + d + 1];
        float v00 = acc[j][0] + b0, v01 = acc[j][1] + b1;
        float v10 = acc[j][2] + b0, v11 = acc[j][3] + b1;
        if (p == 0) {
            v00 *= LOG2E; v01 *= LOG2E; v10 *= LOG2E; v11 *= LOG2E;
            *(__half2*)&g_Qh[((size_t)bh * NTOK + nA) * 8 + d] = __floats2half2_rn(v00, v01);
            *(__half2*)&g_Qh[((size_t)bh * NTOK + nB) * 8 + d] = __floats2half2_rn(v10, v11);
        } else if (p == 1) {
            *(__half2*)&g_Kh[((size_t)bh * NTOK + nA) * 8 + d] = __floats2half2_rn(v00, v01);
            *(__half2*)&g_Kh[((size_t)bh * NTOK + nB) * 8 + d] = __floats2half2_rn(v10, v11);
        } else {
            __half* vt0 = g_VT + ((size_t)bh * 8 + d)     * NTOK;
            __half* vt1 = g_VT + ((size_t)bh * 8 + d + 1) * NTOK;
            vt0[nA] = __float2half_rn(v00);
            vt1[nA] = __float2half_rn(v01);
            vt0[nB] = __float2half_rn(v10);
            vt1[nB] = __float2half_rn(v11);
        }
    }
}

// ============================================================================
// Kernel 2: HMMA attention, R14 CTA shape + n-split for balance.
// 512 CTAs = bh(8) x mb(32 blocks of 128 m) x n-half(2); 256 threads (8 warps).
// Each CTA streams 4 slabs (half of n) and writes UNNORMALIZED num/den
// partials; out_kernel sums the two halves. Math identical to R13/R14.
// ============================================================================
#define VPAD 520   // sVT row stride in halves

__global__ void __launch_bounds__(256, 2) attn_kernel()
{
    __shared__ __align__(16) __half sQ[512 * 8];      // 8 KB
    __shared__ __align__(16) __half sVT[8 * VPAD];    // 8.1 KB

    const int tid  = threadIdx.x;
    const int warp = tid >> 5;
    const int lane = tid & 31;
    const int nh   = blockIdx.x & 1;         // n-half
    const int mb   = (blockIdx.x >> 1) & 31;
    const int bh   = blockIdx.x >> 6;
    const int m0   = mb * 128 + warp * 16;
    const int g    = lane >> 2;
    const int q4   = lane & 3;
    const uint32_t bOnes = (g == 0) ? 0x3C003C00u : 0u;

    const __half* Kbase = g_Kh + (size_t)bh * NTOK * 8;
    const uint32_t aK0 = *(const uint32_t*)(Kbase + (m0 + g) * 8 + q4 * 2);
    const uint32_t aK1 = *(const uint32_t*)(Kbase + (m0 + g + 8) * 8 + q4 * 2);

    float o0 = 0.f, o1 = 0.f, o2 = 0.f, o3 = 0.f;   // E·V accum
    float p0 = 0.f, p1 = 0.f, p2 = 0.f, p3 = 0.f;   // den accum (col 0)

    const int vd = tid >> 5;
    const int vj = tid & 31;

    for (int s = 0; s < 4; ++s) {
        const int ns = nh * 4 + s;
        __syncthreads();
        // stage Q slab: 512 tokens x 8 halves = 512 float4
        {
            const float4* Qs = (const float4*)(g_Qh + (size_t)bh * NTOK * 8 + ns * 512 * 8);
            ((float4*)sQ)[tid]       = Qs[tid];
            ((float4*)sQ)[tid + 256] = Qs[tid + 256];
        }
        // stage V slab: 8 rows x 64 float4
        {
            const float4* Vs = (const float4*)(g_VT + (size_t)(bh * 8 + vd) * NTOK + ns * 512);
            float4* dst = (float4*)(sVT + vd * VPAD);
            dst[vj]      = Vs[vj];
            dst[vj + 32] = Vs[vj + 32];
        }
        __syncthreads();

#pragma unroll 4
        for (int p = 0; p < 32; ++p) {
            const int n0 = p * 16;
            uint32_t bQ0 = *(const uint32_t*)(sQ + (n0 + g) * 8 + q4 * 2);
            uint32_t bQ1 = *(const uint32_t*)(sQ + (n0 + 8 + g) * 8 + q4 * 2);
            uint32_t bV0 = *(const uint32_t*)(sVT + g * VPAD + n0 + q4 * 2);
            uint32_t bV1 = *(const uint32_t*)(sVT + g * VPAD + n0 + 8 + q4 * 2);

            uint32_t e0, e1, e2, e3;
            asm volatile(
                "mma.sync.aligned.m16n8k8.row.col.f16.f16.f16.f16 "
                "{%0,%1}, {%2,%3}, {%4}, {%5,%6};"
                : "=r"(e0), "=r"(e1)
                : "r"(aK0), "r"(aK1), "r"(bQ0), "r"(0u), "r"(0u));
            asm volatile(
                "mma.sync.aligned.m16n8k8.row.col.f16.f16.f16.f16 "
                "{%0,%1}, {%2,%3}, {%4}, {%5,%6};"
                : "=r"(e2), "=r"(e3)
                : "r"(aK0), "r"(aK1), "r"(bQ1), "r"(0u), "r"(0u));

            asm("ex2.approx.f16x2 %0, %1;" : "=r"(e0) : "r"(e0));
            asm("ex2.approx.f16x2 %0, %1;" : "=r"(e1) : "r"(e1));
            asm("ex2.approx.f16x2 %0, %1;" : "=r"(e2) : "r"(e2));
            asm("ex2.approx.f16x2 %0, %1;" : "=r"(e3) : "r"(e3));

            asm volatile(
                "mma.sync.aligned.m16n8k16.row.col.f32.f16.f16.f32 "
                "{%0,%1,%2,%3}, {%4,%5,%6,%7}, {%8,%9}, {%0,%1,%2,%3};"
                : "+f"(o0), "+f"(o1), "+f"(o2), "+f"(o3)
                : "r"(e0), "r"(e1), "r"(e2), "r"(e3), "r"(bV0), "r"(bV1));
            asm volatile(
                "mma.sync.aligned.m16n8k16.row.col.f32.f16.f16.f32 "
                "{%0,%1,%2,%3}, {%4,%5,%6,%7}, {%8,%9}, {%0,%1,%2,%3};"
                : "+f"(p0), "+f"(p1), "+f"(p2), "+f"(p3)
                : "r"(e0), "r"(e1), "r"(e2), "r"(e3), "r"(bOnes), "r"(bOnes));
        }
    }

    // write unnormalized partials for this n-half
    const size_t baseA = ((size_t)(nh * BH_CNT + bh) * NTOK + m0 + g);
    const size_t baseB = baseA + 8;
    *(float2*)(g_Pn + baseA * 8 + q4 * 2) = make_float2(o0, o1);
    *(float2*)(g_Pn + baseB * 8 + q4 * 2) = make_float2(o2, o3);
    if (q4 == 0) {
        g_Pd[baseA] = p0;    // den row g   (col 0 -> acc c0 of q4==0 lanes)
        g_Pd[baseB] = p2;    // den row g+8
    }
    (void)p1; (void)p3;
}

// ============================================================================
// Kernel 3: sum n-half partials, normalize, Wo projection + gamma + residual.
// ============================================================================
__global__ void __launch_bounds__(256) out_kernel(
    const float* __restrict__ x,
    const float* __restrict__ Wo, const float* __restrict__ bo,
    const float* __restrict__ gamma,
    float* __restrict__ out)
{
    __shared__ float wo_s[256];
    __shared__ float bo_s[32];
    __shared__ float gam_s;

    const int t  = blockIdx.x * 256 + threadIdx.x;
    const int m  = t & 4095;
    const int bh = (t >> 12) & 7;
    const int eh = t >> 15;
    const int b  = bh >> 2;
    const int h  = bh & 3;

    wo_s[threadIdx.x] = Wo[h * 512 + eh * 256 + threadIdx.x];
    if (threadIdx.x < 32) bo_s[threadIdx.x] = bo[h * 64 + eh * 32 + threadIdx.x];
    if (threadIdx.x == 0) gam_s = gamma[h];
    __syncthreads();

    const size_t i0 = ((size_t)bh * NTOK + m);
    const size_t i1 = ((size_t)(BH_CNT + bh) * NTOK + m);
    const float4* n0a = (const float4*)(g_Pn + i0 * 8);
    const float4* n1a = (const float4*)(g_Pn + i1 * 8);
    float4 a0 = n0a[0], a1 = n0a[1];
    float4 b0 = n1a[0], b1 = n1a[1];
    const float den = g_Pd[i0] + g_Pd[i1];
    const float rden = 1.0f / den;

    float o[8] = {(a0.x + b0.x) * rden, (a0.y + b0.y) * rden,
                  (a0.z + b0.z) * rden, (a0.w + b0.w) * rden,
                  (a1.x + b1.x) * rden, (a1.y + b1.y) * rden,
                  (a1.z + b1.z) * rden, (a1.w + b1.w) * rden};

    const float gam = gam_s;
#pragma unroll 4
    for (int e = 0; e < 32; ++e) {
        float y = bo_s[e];
#pragma unroll
        for (int d = 0; d < 8; ++d) y += wo_s[e * 8 + d] * o[d];
        int idx = b * (256 * NTOK) + (h * 64 + eh * 32 + e) * NTOK + m;
        out[idx] = gam * y + x[idx];
    }
}

// ============================================================================
extern "C" void kernel_launch(void* const* d_in, const int* in_sizes, int n_in,
                              void* d_out, int out_size)
{
    const float* x     = (const float*)d_in[0];
    const float* Wq    = (const float*)d_in[1];
    const float* bq    = (const float*)d_in[2];
    const float* Wk    = (const float*)d_in[3];
    const float* bk    = (const float*)d_in[4];
    const float* Wv    = (const float*)d_in[5];
    const float* bv    = (const float*)d_in[6];
    const float* Wo    = (const float*)d_in[7];
    const float* bo    = (const float*)d_in[8];
    const float* gamma = (const float*)d_in[9];
    float* out = (float*)d_out;

    qkv_kernel<<<256, 256>>>(x, Wq, bq, Wk, bk, Wv, bv);
    attn_kernel<<<512, 256>>>();
    out_kernel<<<256, 256>>>(x, Wo, bo, gamma, out);
}

// round 17
// speedup vs baseline: 1.2779x; 1.0623x over previous
#include <cuda_runtime.h>
#include <cuda_fp16.h>
#include <cstdint>

// ---------------- problem constants ----------------------------------------
// B=2, C=256, N=4096, NUM_HEAD=4, D=8, AT_HEAD=64, BH=8
#define NTOK   4096
#define BH_CNT 8
#define LOG2E  1.4426950408889634f

// ---------------- device scratch (no allocation allowed) -------------------
__device__ __half g_Qh[BH_CNT * NTOK * 8];
__device__ __half g_Kh[BH_CNT * NTOK * 8];
__device__ __half g_VT[BH_CNT * 8 * NTOK];
// attention partials per n-quarter: unnormalized numerators + denominators
__device__ float  g_Pn[4 * BH_CNT * NTOK * 8];
__device__ float  g_Pd[4 * BH_CNT * NTOK];

// ============================================================================
// Kernel 1: HMMA QKV projection; x staged via LDG.128 (4 tokens/load) for MLP.
// C^T[n][96] = X^T[n][256] · W^T[256][96]; emits f16 q/k ([n][8]) and vT.
// ============================================================================
#define XS_STRIDE 264   // halves per xs row

__global__ void __launch_bounds__(256, 2) qkv_kernel(
    const float* __restrict__ x,
    const float* __restrict__ Wq, const float* __restrict__ bq,
    const float* __restrict__ Wk, const float* __restrict__ bk,
    const float* __restrict__ Wv, const float* __restrict__ bv)
{
    __shared__ __align__(16) __half    xs[32 * XS_STRIDE];  // 16.9 KB
    __shared__ __align__(16) uint32_t  ws32[32 * 104];      // 13.3 KB
    __shared__ float bias_s[96];

    const int b    = blockIdx.x >> 7;
    const int n0   = (blockIdx.x & 127) * 32;
    const int tid  = threadIdx.x;
    const int warp = tid >> 5;
    const int lane = tid & 31;
    const int g    = lane >> 2;
    const int q4   = lane & 3;
    const int mt   = warp & 1;
    const int nh   = warp >> 1;

    if (tid < 96) {
        float bv_;
        if (tid < 32)      bv_ = __ldg(&bq[tid]);
        else if (tid < 64) bv_ = __ldg(&bk[tid - 32]);
        else               bv_ = __ldg(&bv[tid - 64]);
        bias_s[tid] = bv_;
    }

    // stage x^T tile: LDG.128 over n (4 tokens), c-pairs packed to half2
    {
        const int nq4 = tid & 7;          // n-quad (4 tokens)
        const int cg  = tid >> 3;         // 0..31, 8 channels each
        const float* xb = x + (size_t)(b * 256 + cg * 8) * NTOK + n0 + nq4 * 4;
#pragma unroll
        for (int cp = 0; cp < 4; ++cp) {
            float4 r0 = __ldg((const float4*)(xb + (size_t)(2 * cp)     * NTOK));
            float4 r1 = __ldg((const float4*)(xb + (size_t)(2 * cp + 1) * NTOK));
            int c = cg * 8 + cp * 2;
            *(__half2*)&xs[(nq4 * 4 + 0) * XS_STRIDE + c] = __floats2half2_rn(r0.x, r1.x);
            *(__half2*)&xs[(nq4 * 4 + 1) * XS_STRIDE + c] = __floats2half2_rn(r0.y, r1.y);
            *(__half2*)&xs[(nq4 * 4 + 2) * XS_STRIDE + c] = __floats2half2_rn(r0.z, r1.z);
            *(__half2*)&xs[(nq4 * 4 + 3) * XS_STRIDE + c] = __floats2half2_rn(r0.w, r1.w);
        }
    }

    float acc[3][4];
#pragma unroll
    for (int j = 0; j < 3; ++j)
#pragma unroll
        for (int i = 0; i < 4; ++i) acc[j][i] = 0.0f;

    for (int kc = 0; kc < 4; ++kc) {
        __syncthreads();
#pragma unroll
        for (int t = 0; t < 6; ++t) {
            int idx = tid + t * 256;
            int r   = idx >> 4;
            int kq  = idx & 15;
            const float* base = (r < 32) ? Wq : ((r < 64) ? Wk : Wv);
            float4 w = __ldg((const float4*)(base + (r & 31) * 256 + kc * 64) + kq);
            __half2 h0 = __floats2half2_rn(w.x, w.y);
            __half2 h1 = __floats2half2_rn(w.z, w.w);
            ws32[(kq * 2)     * 104 + r] = *(uint32_t*)&h0;
            ws32[(kq * 2 + 1) * 104 + r] = *(uint32_t*)&h1;
        }
        __syncthreads();

#pragma unroll
        for (int k8 = 0; k8 < 8; ++k8) {
            const int cbase = kc * 64 + k8 * 8 + 2 * q4;
            uint32_t a0 = *(const uint32_t*)&xs[(mt * 16 + g)     * XS_STRIDE + cbase];
            uint32_t a1 = *(const uint32_t*)&xs[(mt * 16 + g + 8) * XS_STRIDE + cbase];
            const uint32_t* wrow = &ws32[(k8 * 4 + q4) * 104];
#pragma unroll
            for (int j = 0; j < 3; ++j) {
                uint32_t bf = wrow[(nh * 3 + j) * 8 + g];
                asm volatile(
                    "mma.sync.aligned.m16n8k8.row.col.f32.f16.f16.f32 "
                    "{%0,%1,%2,%3}, {%4,%5}, {%6}, {%0,%1,%2,%3};"
                    : "+f"(acc[j][0]), "+f"(acc[j][1]), "+f"(acc[j][2]), "+f"(acc[j][3])
                    : "r"(a0), "r"(a1), "r"(bf));
            }
        }
    }

    const int nA = n0 + mt * 16 + g;
    const int nB = nA + 8;
#pragma unroll
    for (int j = 0; j < 3; ++j) {
        int tile = nh * 3 + j;
        int p = tile >> 2;
        int h = tile & 3;
        int d = 2 * q4;
        int bh = b * 4 + h;
        float b0 = bias_s[tile * 8 + d];
        float b1 = bias_s[tile * 8 + d + 1];
        float v00 = acc[j][0] + b0, v01 = acc[j][1] + b1;
        float v10 = acc[j][2] + b0, v11 = acc[j][3] + b1;
        if (p == 0) {
            v00 *= LOG2E; v01 *= LOG2E; v10 *= LOG2E; v11 *= LOG2E;
            *(__half2*)&g_Qh[((size_t)bh * NTOK + nA) * 8 + d] = __floats2half2_rn(v00, v01);
            *(__half2*)&g_Qh[((size_t)bh * NTOK + nB) * 8 + d] = __floats2half2_rn(v10, v11);
        } else if (p == 1) {
            *(__half2*)&g_Kh[((size_t)bh * NTOK + nA) * 8 + d] = __floats2half2_rn(v00, v01);
            *(__half2*)&g_Kh[((size_t)bh * NTOK + nB) * 8 + d] = __floats2half2_rn(v10, v11);
        } else {
            __half* vt0 = g_VT + ((size_t)bh * 8 + d)     * NTOK;
            __half* vt1 = g_VT + ((size_t)bh * 8 + d + 1) * NTOK;
            vt0[nA] = __float2half_rn(v00);
            vt1[nA] = __float2half_rn(v01);
            vt0[nB] = __float2half_rn(v10);
            vt1[nB] = __float2half_rn(v11);
        }
    }
}

// ============================================================================
// Kernel 2: HMMA attention, R14 CTA shape + n-QUARTER split for balance.
// 1024 CTAs = bh(8) x mb(32 blocks of 128 m) x n-quarter(4); 256 thr, 8 warps.
// Each CTA streams 2 slabs and writes UNNORMALIZED num/den partials;
// out_kernel sums the four quarters. Math identical to R13-R16.
// ============================================================================
#define VPAD 520   // sVT row stride in halves

__global__ void __launch_bounds__(256, 2) attn_kernel()
{
    __shared__ __align__(16) __half sQ[512 * 8];      // 8 KB
    __shared__ __align__(16) __half sVT[8 * VPAD];    // 8.1 KB

    const int tid  = threadIdx.x;
    const int warp = tid >> 5;
    const int lane = tid & 31;
    const int nq   = blockIdx.x & 3;          // n-quarter
    const int mb   = (blockIdx.x >> 2) & 31;
    const int bh   = blockIdx.x >> 7;
    const int m0   = mb * 128 + warp * 16;
    const int g    = lane >> 2;
    const int q4   = lane & 3;
    const uint32_t bOnes = (g == 0) ? 0x3C003C00u : 0u;

    const __half* Kbase = g_Kh + (size_t)bh * NTOK * 8;
    const uint32_t aK0 = *(const uint32_t*)(Kbase + (m0 + g) * 8 + q4 * 2);
    const uint32_t aK1 = *(const uint32_t*)(Kbase + (m0 + g + 8) * 8 + q4 * 2);

    float o0 = 0.f, o1 = 0.f, o2 = 0.f, o3 = 0.f;   // E·V accum
    float p0 = 0.f, p1 = 0.f, p2 = 0.f, p3 = 0.f;   // den accum (col 0)

    const int vd = tid >> 5;
    const int vj = tid & 31;

    for (int s = 0; s < 2; ++s) {
        const int ns = nq * 2 + s;
        __syncthreads();
        // stage Q slab: 512 tokens x 8 halves = 512 float4
        {
            const float4* Qs = (const float4*)(g_Qh + (size_t)bh * NTOK * 8 + ns * 512 * 8);
            ((float4*)sQ)[tid]       = Qs[tid];
            ((float4*)sQ)[tid + 256] = Qs[tid + 256];
        }
        // stage V slab: 8 rows x 64 float4
        {
            const float4* Vs = (const float4*)(g_VT + (size_t)(bh * 8 + vd) * NTOK + ns * 512);
            float4* dst = (float4*)(sVT + vd * VPAD);
            dst[vj]      = Vs[vj];
            dst[vj + 32] = Vs[vj + 32];
        }
        __syncthreads();

#pragma unroll 4
        for (int p = 0; p < 32; ++p) {
            const int n0 = p * 16;
            uint32_t bQ0 = *(const uint32_t*)(sQ + (n0 + g) * 8 + q4 * 2);
            uint32_t bQ1 = *(const uint32_t*)(sQ + (n0 + 8 + g) * 8 + q4 * 2);
            uint32_t bV0 = *(const uint32_t*)(sVT + g * VPAD + n0 + q4 * 2);
            uint32_t bV1 = *(const uint32_t*)(sVT + g * VPAD + n0 + 8 + q4 * 2);

            uint32_t e0, e1, e2, e3;
            asm volatile(
                "mma.sync.aligned.m16n8k8.row.col.f16.f16.f16.f16 "
                "{%0,%1}, {%2,%3}, {%4}, {%5,%6};"
                : "=r"(e0), "=r"(e1)
                : "r"(aK0), "r"(aK1), "r"(bQ0), "r"(0u), "r"(0u));
            asm volatile(
                "mma.sync.aligned.m16n8k8.row.col.f16.f16.f16.f16 "
                "{%0,%1}, {%2,%3}, {%4}, {%5,%6};"
                : "=r"(e2), "=r"(e3)
                : "r"(aK0), "r"(aK1), "r"(bQ1), "r"(0u), "r"(0u));

            asm("ex2.approx.f16x2 %0, %1;" : "=r"(e0) : "r"(e0));
            asm("ex2.approx.f16x2 %0, %1;" : "=r"(e1) : "r"(e1));
            asm("ex2.approx.f16x2 %0, %1;" : "=r"(e2) : "r"(e2));
            asm("ex2.approx.f16x2 %0, %1;" : "=r"(e3) : "r"(e3));

            asm volatile(
                "mma.sync.aligned.m16n8k16.row.col.f32.f16.f16.f32 "
                "{%0,%1,%2,%3}, {%4,%5,%6,%7}, {%8,%9}, {%0,%1,%2,%3};"
                : "+f"(o0), "+f"(o1), "+f"(o2), "+f"(o3)
                : "r"(e0), "r"(e1), "r"(e2), "r"(e3), "r"(bV0), "r"(bV1));
            asm volatile(
                "mma.sync.aligned.m16n8k16.row.col.f32.f16.f16.f32 "
                "{%0,%1,%2,%3}, {%4,%5,%6,%7}, {%8,%9}, {%0,%1,%2,%3};"
                : "+f"(p0), "+f"(p1), "+f"(p2), "+f"(p3)
                : "r"(e0), "r"(e1), "r"(e2), "r"(e3), "r"(bOnes), "r"(bOnes));
        }
    }

    // write unnormalized partials for this n-quarter
    const size_t baseA = ((size_t)(nq * BH_CNT + bh) * NTOK + m0 + g);
    const size_t baseB = baseA + 8;
    *(float2*)(g_Pn + baseA * 8 + q4 * 2) = make_float2(o0, o1);
    *(float2*)(g_Pn + baseB * 8 + q4 * 2) = make_float2(o2, o3);
    if (q4 == 0) {
        g_Pd[baseA] = p0;    // den row g
        g_Pd[baseB] = p2;    // den row g+8
    }
    (void)p1; (void)p3;
}

// ============================================================================
// Kernel 3: sum n-quarter partials, normalize, Wo proj + gamma + residual.
// ============================================================================
__global__ void __launch_bounds__(256) out_kernel(
    const float* __restrict__ x,
    const float* __restrict__ Wo, const float* __restrict__ bo,
    const float* __restrict__ gamma,
    float* __restrict__ out)
{
    __shared__ float wo_s[256];
    __shared__ float bo_s[32];
    __shared__ float gam_s;

    const int t  = blockIdx.x * 256 + threadIdx.x;
    const int m  = t & 4095;
    const int bh = (t >> 12) & 7;
    const int eh = t >> 15;
    const int b  = bh >> 2;
    const int h  = bh & 3;

    wo_s[threadIdx.x] = Wo[h * 512 + eh * 256 + threadIdx.x];
    if (threadIdx.x < 32) bo_s[threadIdx.x] = bo[h * 64 + eh * 32 + threadIdx.x];
    if (threadIdx.x == 0) gam_s = gamma[h];
    __syncthreads();

    float num[8] = {0, 0, 0, 0, 0, 0, 0, 0};
    float den = 0.0f;
#pragma unroll
    for (int q = 0; q < 4; ++q) {
        const size_t iq = ((size_t)(q * BH_CNT + bh) * NTOK + m);
        const float4* nq = (const float4*)(g_Pn + iq * 8);
        float4 a = nq[0], c = nq[1];
        num[0] += a.x; num[1] += a.y; num[2] += a.z; num[3] += a.w;
        num[4] += c.x; num[5] += c.y; num[6] += c.z; num[7] += c.w;
        den += g_Pd[iq];
    }
    const float rden = 1.0f / den;
    float o[8];
#pragma unroll
    for (int d = 0; d < 8; ++d) o[d] = num[d] * rden;

    const float gam = gam_s;
#pragma unroll 4
    for (int e = 0; e < 32; ++e) {
        float y = bo_s[e];
#pragma unroll
        for (int d = 0; d < 8; ++d) y += wo_s[e * 8 + d] * o[d];
        int idx = b * (256 * NTOK) + (h * 64 + eh * 32 + e) * NTOK + m;
        out[idx] = gam * y + x[idx];
    }
}

// ============================================================================
extern "C" void kernel_launch(void* const* d_in, const int* in_sizes, int n_in,
                              void* d_out, int out_size)
{
    const float* x     = (const float*)d_in[0];
    const float* Wq    = (const float*)d_in[1];
    const float* bq    = (const float*)d_in[2];
    const float* Wk    = (const float*)d_in[3];
    const float* bk    = (const float*)d_in[4];
    const float* Wv    = (const float*)d_in[5];
    const float* bv    = (const float*)d_in[6];
    const float* Wo    = (const float*)d_in[7];
    const float* bo    = (const float*)d_in[8];
    const float* gamma = (const float*)d_in[9];
    float* out = (float*)d_out;

    qkv_kernel<<<256, 256>>>(x, Wq, bq, Wk, bk, Wv, bv);
    attn_kernel<<<1024, 256>>>();
    out_kernel<<<256, 256>>>(x, Wo, bo, gamma, out);
}